// round 6
// baseline (speedup 1.0000x reference)
#include <cuda_runtime.h>
#include <cuda_bf16.h>
#include <cstdint>

#define BATCH 8192
#define NNODE 30
#define FEAT  256

__device__ __nv_bfloat16 g_w1h[FEAT * FEAT], g_w1l[FEAT * FEAT];
__device__ __nv_bfloat16 g_w2h[FEAT * FEAT], g_w2l[FEAT * FEAT];

// ==================== helpers ====================
__device__ __forceinline__ uint32_t smem_to_u32(const void* p) {
    uint32_t a;
    asm("{ .reg .u64 t; cvta.to.shared.u64 t, %1; cvt.u32.u64 %0, t; }" : "=r"(a) : "l"(p));
    return a;
}
__device__ __forceinline__ void cpasync16(uint32_t saddr, const void* g) {
    asm volatile("cp.async.cg.shared.global [%0], [%1], 16;" :: "r"(saddr), "l"(g));
}
__device__ __forceinline__ void ldsm4(uint32_t* r, uint32_t addr) {
    asm volatile("ldmatrix.sync.aligned.m8n8.x4.shared.b16 {%0,%1,%2,%3}, [%4];"
        : "=r"(r[0]), "=r"(r[1]), "=r"(r[2]), "=r"(r[3]) : "r"(addr));
}
__device__ __forceinline__ void mma_bf16(float* d, const uint32_t* a, uint32_t b0, uint32_t b1) {
    asm volatile(
        "mma.sync.aligned.m16n8k16.row.col.f32.bf16.bf16.f32 "
        "{%0,%1,%2,%3}, {%4,%5,%6,%7}, {%8,%9}, {%0,%1,%2,%3};"
        : "+f"(d[0]), "+f"(d[1]), "+f"(d[2]), "+f"(d[3])
        : "r"(a[0]), "r"(a[1]), "r"(a[2]), "r"(a[3]), "r"(b0), "r"(b1));
}

// =====================================================================
__global__ void prep_w(const float* __restrict__ W1, const float* __restrict__ W2,
                       __nv_bfloat16* __restrict__ w1h, __nv_bfloat16* __restrict__ w1l,
                       __nv_bfloat16* __restrict__ w2h, __nv_bfloat16* __restrict__ w2l) {
    const int n = blockIdx.x, k = threadIdx.x;
    float v1 = W1[k * 256 + n];
    __nv_bfloat16 h1 = __float2bfloat16_rn(v1);
    w1h[n * 256 + k] = h1;
    w1l[n * 256 + k] = __float2bfloat16_rn(v1 - __bfloat162float(h1));
    float v2 = W2[k * 256 + n];
    __nv_bfloat16 h2 = __float2bfloat16_rn(v2);
    w2h[n * 256 + k] = h2;
    w2l[n * 256 + k] = __float2bfloat16_rn(v2 - __bfloat162float(h2));
}

// =====================================================================
// MEGA: 4 batches (120 rows pad 128) per CTA, 512 threads / 16 warps.
// RA  [0,131072):      A split: 4 chunks [128x64]bf16 hi (16KB ea, SW) ; lo at +65536
// RW  [131072,163840): W stages (GEMM1: 2x16KB; GEMM2q: 2x8KB+8KB)
//                      phase A: x stages 2x30720 (overlaps RW+U2)
// U2  [163840,196608): u2 quarter fp32 [128x64]
// ADJ [196608,211968): 4 x [30 x 32] f32
// B1  [211968,212992): bias1
// RED [212992,213952): 4*30*2 partial dots (accumulated)
// =====================================================================
#define SM_RA   0u
#define SM_RW   131072u
#define SM_U2   163840u
#define SM_ADJ  196608u
#define SM_B1   211968u
#define SM_RED  212992u
#define SMEM_TOTAL 214016

__global__ __launch_bounds__(512, 1)
void mega(const float* __restrict__ x, const float* __restrict__ graph,
          const float* __restrict__ b1g, const float* __restrict__ b2g,
          const float* __restrict__ wling, const float* __restrict__ bling,
          const float* __restrict__ Wheadg, const float* __restrict__ bheadg,
          const __nv_bfloat16* __restrict__ W1h, const __nv_bfloat16* __restrict__ W1l,
          const __nv_bfloat16* __restrict__ W2h, const __nv_bfloat16* __restrict__ W2l,
          float* __restrict__ out) {
    extern __shared__ char smem[];
    const uint32_t sb = smem_to_u32(smem);
    const int tid = threadIdx.x, lane = tid & 31, wid = tid >> 5;
    const int warp_m = wid & 3, warp_n = wid >> 2;    // 4 x 4 warp grid
    const size_t b0 = (size_t)blockIdx.x * 4;
    float* adj_s = (float*)(smem + SM_ADJ);
    float* red   = (float*)(smem + SM_RED);

    // ---------------- setup: adj, bias, pad rows, red=0 ----------------
    for (int e = tid; e < 3600; e += 512) {
        int b = e / 900, i = e - b * 900;
        const float* gp = graph + (b0 + b) * 4500 + i;
        float s = 0.2f * (gp[0] + gp[900] + gp[1800] + gp[2700] + gp[3600]);
        adj_s[b * 960 + (i / 30) * 32 + (i % 30)] = s;
    }
    if (tid < 256) ((float*)(smem + SM_B1))[tid] = b1g[tid];
    if (tid < 240) red[tid] = 0.f;
    {   // zero pad rows 120..127 of all 4 A chunks (hi+lo)
        int chunk = tid >> 7, hl = (tid >> 6) & 1, rr = 120 + ((tid >> 3) & 7), seg = tid & 7;
        uint32_t off = (uint32_t)chunk * 16384u + (uint32_t)(rr * 128)
                     + (((uint32_t)seg * 16u) ^ ((uint32_t)(rr & 7) << 4))
                     + (uint32_t)hl * 65536u;
        *(uint4*)(smem + SM_RA + off) = make_uint4(0, 0, 0, 0);
    }

    // ---------------- Phase A: y1 = adj @ x -> bf16 split ----------------
    auto xload = [&](int c) {
        const float* gx = x + (b0 * 30) * 256 + c * 64;
        uint32_t st = sb + SM_RW + (uint32_t)(c & 1) * 30720u;
        for (int u = tid; u < 1920; u += 512) {
            int row = u >> 4, seg = u & 15;
            cpasync16(st + (uint32_t)(row * 256 + seg * 16), gx + (size_t)row * 256 + seg * 4);
        }
        asm volatile("cp.async.commit_group;" ::: "memory");
    };
    xload(0);
    xload(1);

    const int pb = tid >> 7;                 // batch 0..3
    const int pg = (tid >> 5) & 3;           // row group
    const int pcp = tid & 31;                // col pair
    const int pstart = (pg <= 1) ? pg * 8 : 16 + (pg - 2) * 7;
    const int pend = (pg <= 1) ? pstart + 8 : pstart + 7;
    __syncthreads();

    #pragma unroll 1
    for (int c = 0; c < 4; ++c) {
        if (c < 3) asm volatile("cp.async.wait_group 1;" ::: "memory");
        else       asm volatile("cp.async.wait_group 0;" ::: "memory");
        __syncthreads();
        const float* xs = (const float*)(smem + SM_RW + (c & 1) * 30720);
        float2 xk[30];
        #pragma unroll
        for (int k = 0; k < 30; ++k)
            xk[k] = *(const float2*)(xs + (pb * 30 + k) * 64 + pcp * 2);
        const float* ar = adj_s + pb * 960;
        #pragma unroll 1
        for (int i = pstart; i < pend; ++i) {
            float s0 = 0.f, s1 = 0.f;
            #pragma unroll
            for (int k = 0; k < 30; ++k) {
                float a = ar[i * 32 + k];
                s0 = fmaf(a, xk[k].x, s0);
                s1 = fmaf(a, xk[k].y, s1);
            }
            int r = pb * 30 + i;
            __nv_bfloat16 h0 = __float2bfloat16_rn(s0), h1 = __float2bfloat16_rn(s1);
            __nv_bfloat162 hv; hv.x = h0; hv.y = h1;
            __nv_bfloat162 lv;
            lv.x = __float2bfloat16_rn(s0 - __bfloat162float(h0));
            lv.y = __float2bfloat16_rn(s1 - __bfloat162float(h1));
            uint32_t B = (uint32_t)(pcp * 4);
            uint32_t off = (uint32_t)c * 16384u + (uint32_t)(r * 128)
                         + (B ^ ((uint32_t)(r & 7) << 4));
            *(__nv_bfloat162*)(smem + SM_RA + off)          = hv;
            *(__nv_bfloat162*)(smem + SM_RA + 65536u + off) = lv;
        }
        __syncthreads();
        if (c + 2 < 4) xload(c + 2);
    }

    // ---------------- common ldmatrix addressing ----------------
    const int matv = lane >> 3;
    const int rA0 = warp_m * 32 + (matv & 1) * 8 + (lane & 7);
    const int kAoff = (matv >> 1) * 16;
    const uint32_t xorA = (uint32_t)((lane & 7) << 4);
    const uint32_t xorB = (uint32_t)((lane & 3) << 4);

    // ================= GEMM1: full N=256, acc[2][8][4] =================
    {
        float acc[2][8][4];
        #pragma unroll
        for (int m = 0; m < 2; ++m)
            #pragma unroll
            for (int j = 0; j < 8; ++j)
                #pragma unroll
                for (int q = 0; q < 4; ++q) acc[m][j][q] = 0.f;

        auto wload = [&](int wc) {
            uint32_t st = sb + SM_RW + (uint32_t)(wc & 1) * 32768u;
            #pragma unroll
            for (int u = tid; u < 1024; u += 512) {
                int n = u >> 2, seg = u & 3;
                uint32_t off = (uint32_t)(n * 64) + (((uint32_t)seg * 16u) ^ ((uint32_t)(n & 3) << 4));
                size_t go = (size_t)n * 256 + (size_t)wc * 32 + seg * 8;
                cpasync16(st + off,          W1h + go);
                cpasync16(st + 16384u + off, W1l + go);
            }
            asm volatile("cp.async.commit_group;" ::: "memory");
        };
        wload(0);
        wload(1);
        const int rB0 = warp_n * 64 + matv * 8 + (lane & 7);

        #pragma unroll 1
        for (int wc = 0; wc < 8; ++wc) {
            if (wc < 7) asm volatile("cp.async.wait_group 1;" ::: "memory");
            else        asm volatile("cp.async.wait_group 0;" ::: "memory");
            __syncthreads();
            const uint32_t wst = sb + SM_RW + (uint32_t)(wc & 1) * 32768u;
            #pragma unroll
            for (int ks2 = 0; ks2 < 2; ++ks2) {
                const int K = wc * 2 + ks2;
                const uint32_t abase = sb + SM_RA + (uint32_t)(K >> 2) * 16384u;
                const uint32_t aco = ((uint32_t)((K & 3) * 32 + kAoff)) ^ xorA;
                uint32_t ah_f[2][4], al_f[2][4];
                #pragma unroll
                for (int mt = 0; mt < 2; ++mt) {
                    uint32_t ro = (uint32_t)((rA0 + mt * 16) * 128);
                    ldsm4(ah_f[mt], abase + ro + aco);
                    ldsm4(al_f[mt], abase + 65536u + ro + aco);
                }
                const uint32_t c0 = ((uint32_t)(ks2 * 32)) ^ xorB;
                const uint32_t c1 = ((uint32_t)(ks2 * 32 + 16)) ^ xorB;
                #pragma unroll
                for (int jb = 0; jb < 2; ++jb) {
                    uint32_t ro = (uint32_t)((rB0 + jb * 32) * 64);
                    uint32_t bh0[4], bh1[4], bl0[4], bl1[4];
                    ldsm4(bh0, wst + ro + c0);
                    ldsm4(bh1, wst + ro + c1);
                    ldsm4(bl0, wst + 16384u + ro + c0);
                    ldsm4(bl1, wst + 16384u + ro + c1);
                    #pragma unroll
                    for (int mt = 0; mt < 2; ++mt)
                        #pragma unroll
                        for (int jj = 0; jj < 4; ++jj) {
                            int j = jb * 4 + jj;
                            mma_bf16(acc[mt][j], ah_f[mt], bh0[jj], bh1[jj]);
                            mma_bf16(acc[mt][j], ah_f[mt], bl0[jj], bl1[jj]);
                            mma_bf16(acc[mt][j], al_f[mt], bh0[jj], bh1[jj]);
                        }
                }
            }
            __syncthreads();
            if (wc + 2 < 8) wload(wc + 2);
        }

        // ------- epilogue: h1 = relu(u1+b1) -> bf16 split into RA -------
        const float* b1s = (const float*)(smem + SM_B1);
        const int g = lane >> 2, cq = (lane & 3) * 2;
        #pragma unroll
        for (int mt = 0; mt < 2; ++mt) {
            int r = warp_m * 32 + mt * 16 + g;
            #pragma unroll
            for (int j = 0; j < 8; ++j) {
                int col = warp_n * 64 + j * 8 + cq;
                float bb0 = b1s[col], bb1 = b1s[col + 1];
                uint32_t chunk = (uint32_t)(col >> 6);
                uint32_t B = (uint32_t)((col & 63) * 2);
                #pragma unroll
                for (int half = 0; half < 2; ++half) {
                    int rr = r + half * 8;
                    float v0 = fmaxf(acc[mt][j][half * 2]     + bb0, 0.f);
                    float v1 = fmaxf(acc[mt][j][half * 2 + 1] + bb1, 0.f);
                    __nv_bfloat16 h0 = __float2bfloat16_rn(v0), h1 = __float2bfloat16_rn(v1);
                    __nv_bfloat162 hv; hv.x = h0; hv.y = h1;
                    __nv_bfloat162 lv;
                    lv.x = __float2bfloat16_rn(v0 - __bfloat162float(h0));
                    lv.y = __float2bfloat16_rn(v1 - __bfloat162float(h1));
                    uint32_t off = chunk * 16384u + (uint32_t)(rr * 128)
                                 + (B ^ ((uint32_t)(rr & 7) << 4));
                    *(__nv_bfloat162*)(smem + SM_RA + off)          = hv;
                    *(__nv_bfloat162*)(smem + SM_RA + 65536u + off) = lv;
                }
            }
        }
    }
    __syncthreads();

    // ================= GEMM2 in 4 N-quarters + fused phase D =================
    const int db = tid >> 7;            // batch
    const int dcidx = tid & 63;         // column within quarter
    const int dihalf = (tid >> 6) & 1;  // i half
    const int dw2 = dcidx >> 5;         // which 32-col warp

    #pragma unroll 1
    for (int q = 0; q < 4; ++q) {
        float acc2[2][2][4];
        #pragma unroll
        for (int m = 0; m < 2; ++m)
            #pragma unroll
            for (int j = 0; j < 2; ++j)
                #pragma unroll
                for (int qq = 0; qq < 4; ++qq) acc2[m][j][qq] = 0.f;

        auto wload2 = [&](int wc) {
            uint32_t st = sb + SM_RW + (uint32_t)(wc & 1) * 16384u;
            int arr = tid >> 8, v = tid & 255;
            int n = v >> 2, seg = v & 3;
            uint32_t off = (uint32_t)(n * 64) + (((uint32_t)seg * 16u) ^ ((uint32_t)(n & 3) << 4));
            size_t go = (size_t)(q * 64 + n) * 256 + (size_t)wc * 32 + seg * 8;
            cpasync16(st + (uint32_t)arr * 8192u + off, (arr ? W2l : W2h) + go);
            asm volatile("cp.async.commit_group;" ::: "memory");
        };
        wload2(0);
        wload2(1);

        #pragma unroll 1
        for (int wc = 0; wc < 8; ++wc) {
            if (wc < 7) asm volatile("cp.async.wait_group 1;" ::: "memory");
            else        asm volatile("cp.async.wait_group 0;" ::: "memory");
            __syncthreads();
            const uint32_t wst = sb + SM_RW + (uint32_t)(wc & 1) * 16384u;
            #pragma unroll
            for (int ks2 = 0; ks2 < 2; ++ks2) {
                const int K = wc * 2 + ks2;
                const uint32_t abase = sb + SM_RA + (uint32_t)(K >> 2) * 16384u;
                const uint32_t aco = ((uint32_t)((K & 3) * 32 + kAoff)) ^ xorA;
                uint32_t ah_f[2][4], al_f[2][4];
                #pragma unroll
                for (int mt = 0; mt < 2; ++mt) {
                    uint32_t ro = (uint32_t)((rA0 + mt * 16) * 128);
                    ldsm4(ah_f[mt], abase + ro + aco);
                    ldsm4(al_f[mt], abase + 65536u + ro + aco);
                }
                // B: 4 matrices {j0k0,j0k1,j1k0,j1k1}
                const int bj = matv >> 1, bk = matv & 1;
                const int brow = warp_n * 16 + bj * 8 + (lane & 7);
                const uint32_t bcol = ((uint32_t)(ks2 * 32 + bk * 16)) ^ xorB;
                uint32_t bh[4], bl[4];
                ldsm4(bh, wst + (uint32_t)(brow * 64) + bcol);
                ldsm4(bl, wst + 8192u + (uint32_t)(brow * 64) + bcol);
                #pragma unroll
                for (int mt = 0; mt < 2; ++mt)
                    #pragma unroll
                    for (int j = 0; j < 2; ++j) {
                        mma_bf16(acc2[mt][j], ah_f[mt], bh[j * 2], bh[j * 2 + 1]);
                        mma_bf16(acc2[mt][j], ah_f[mt], bl[j * 2], bl[j * 2 + 1]);
                        mma_bf16(acc2[mt][j], al_f[mt], bh[j * 2], bh[j * 2 + 1]);
                    }
            }
            __syncthreads();
            if (wc + 2 < 8) wload2(wc + 2);
        }

        // ------- write u2 quarter (fp32) to U2 -------
        {
            float* u2 = (float*)(smem + SM_U2);
            const int g = lane >> 2, cq = (lane & 3) * 2;
            #pragma unroll
            for (int mt = 0; mt < 2; ++mt) {
                int r = warp_m * 32 + mt * 16 + g;
                #pragma unroll
                for (int j = 0; j < 2; ++j) {
                    int col = warp_n * 16 + j * 8 + cq;
                    *(float2*)(u2 + (size_t)r * 64 + col)       = make_float2(acc2[mt][j][0], acc2[mt][j][1]);
                    *(float2*)(u2 + (size_t)(r + 8) * 64 + col) = make_float2(acc2[mt][j][2], acc2[mt][j][3]);
                }
            }
        }
        __syncthreads();

        // ------- phase D quarter: g2 = adj@u2; relu(+b2); dot wlin -------
        {
            const int gcol = q * 64 + dcidx;
            const float b2v = __ldg(b2g + gcol);
            const float wlv = __ldg(wling + gcol);
            const float* u2 = (const float*)(smem + SM_U2);
            float uk[30];
            #pragma unroll
            for (int k = 0; k < 30; ++k)
                uk[k] = u2[(size_t)(db * 30 + k) * 64 + dcidx];
            const float* ar = adj_s + db * 960 + dihalf * 15 * 32;
            #pragma unroll 1
            for (int ii = 0; ii < 15; ++ii) {
                float s = 0.f;
                #pragma unroll
                for (int k = 0; k < 30; ++k)
                    s = fmaf(ar[ii * 32 + k], uk[k], s);
                float p = fmaxf(s + b2v, 0.f) * wlv;
                #pragma unroll
                for (int o = 16; o > 0; o >>= 1) p += __shfl_xor_sync(0xffffffffu, p, o);
                if ((lane & 31) == 0) {
                    int i = dihalf * 15 + ii;
                    red[(db * 30 + i) * 2 + dw2] += p;
                }
            }
        }
        __syncthreads();
    }

    // ---------------- head ----------------
    if (tid < 36) {
        const int b = tid / 9, c = tid - b * 9;
        const float bl = __ldg(bling);
        float s = __ldg(bheadg + c);
        #pragma unroll
        for (int i = 0; i < 30; ++i) {
            float xl = fmaxf(red[(b * 30 + i) * 2] + red[(b * 30 + i) * 2 + 1] + bl, 0.f);
            s = fmaf(xl, __ldg(Wheadg + c * 30 + i), s);
        }
        out[(b0 + b) * 9 + c] = s;
    }
}

// =====================================================================
extern "C" void kernel_launch(void* const* d_in, const int* in_sizes, int n_in,
                              void* d_out, int out_size) {
    const float* real  = (const float*)d_in[0];
    const float* graph = (const float*)d_in[2];
    const float* W1    = (const float*)d_in[3];
    const float* b1    = (const float*)d_in[4];
    const float* W2    = (const float*)d_in[5];
    const float* b2    = (const float*)d_in[6];
    const float* wlin  = (const float*)d_in[7];
    const float* blin  = (const float*)d_in[8];
    const float* Whead = (const float*)d_in[9];
    const float* bhead = (const float*)d_in[10];
    float* out = (float*)d_out;

    __nv_bfloat16 *w1h_p, *w1l_p, *w2h_p, *w2l_p;
    cudaGetSymbolAddress((void**)&w1h_p, g_w1h);
    cudaGetSymbolAddress((void**)&w1l_p, g_w1l);
    cudaGetSymbolAddress((void**)&w2h_p, g_w2h);
    cudaGetSymbolAddress((void**)&w2l_p, g_w2l);

    cudaFuncSetAttribute(mega, cudaFuncAttributeMaxDynamicSharedMemorySize, SMEM_TOTAL);

    prep_w<<<256, 256>>>(W1, W2, w1h_p, w1l_p, w2h_p, w2l_p);
    mega<<<BATCH / 4, 512, SMEM_TOTAL>>>(real, graph, b1, b2, wlin, blin, Whead, bhead,
                                         w1h_p, w1l_p, w2h_p, w2l_p, out);
}

// round 7
// speedup vs baseline: 1.0806x; 1.0806x over previous
#include <cuda_runtime.h>
#include <cuda_bf16.h>
#include <cstdint>

#define BATCH 8192
#define NNODE 30
#define FEAT  256
#define MROWS (BATCH * NNODE)   // 245760

// ---------------- scratch (device globals) ----------------
__device__ float         g_adj[(size_t)BATCH * NNODE * NNODE];  // 29.5 MB
__device__ __nv_bfloat16 g_ah[(size_t)MROWS * FEAT];            // y1 split hi
__device__ __nv_bfloat16 g_al[(size_t)MROWS * FEAT];            // y1 split lo
__device__ __nv_bfloat16 g_hh[(size_t)MROWS * FEAT];            // h1 split hi
__device__ __nv_bfloat16 g_hl[(size_t)MROWS * FEAT];            // h1 split lo
__device__ float         g_u2[(size_t)MROWS * FEAT];            // u2 = h1@W2 fp32
__device__ __nv_bfloat16 g_w1h[FEAT * FEAT], g_w1l[FEAT * FEAT];
__device__ __nv_bfloat16 g_w2h[FEAT * FEAT], g_w2l[FEAT * FEAT];

// ==================== helpers ====================
__device__ __forceinline__ uint32_t smem_to_u32(const void* p) {
    uint32_t a;
    asm("{ .reg .u64 t; cvta.to.shared.u64 t, %1; cvt.u32.u64 %0, t; }" : "=r"(a) : "l"(p));
    return a;
}
__device__ __forceinline__ void cpasync16(uint32_t saddr, const void* g) {
    asm volatile("cp.async.cg.shared.global [%0], [%1], 16;" :: "r"(saddr), "l"(g));
}
__device__ __forceinline__ void ldsm4(uint32_t* r, uint32_t addr) {
    asm volatile("ldmatrix.sync.aligned.m8n8.x4.shared.b16 {%0,%1,%2,%3}, [%4];"
        : "=r"(r[0]), "=r"(r[1]), "=r"(r[2]), "=r"(r[3]) : "r"(addr));
}
__device__ __forceinline__ void mma_bf16(float* d, const uint32_t* a, uint32_t b0, uint32_t b1) {
    asm volatile(
        "mma.sync.aligned.m16n8k16.row.col.f32.bf16.bf16.f32 "
        "{%0,%1,%2,%3}, {%4,%5,%6,%7}, {%8,%9}, {%0,%1,%2,%3};"
        : "+f"(d[0]), "+f"(d[1]), "+f"(d[2]), "+f"(d[3])
        : "r"(a[0]), "r"(a[1]), "r"(a[2]), "r"(a[3]), "r"(b0), "r"(b1));
}
__device__ __forceinline__ unsigned long long pk2(float x, float y) {
    unsigned long long r;
    asm("mov.b64 %0, {%1, %2};" : "=l"(r) : "f"(x), "f"(y));
    return r;
}
__device__ __forceinline__ void upk2(unsigned long long v, float& x, float& y) {
    asm("mov.b64 {%0, %1}, %2;" : "=f"(x), "=f"(y) : "l"(v));
}
__device__ __forceinline__ unsigned long long fma2(unsigned long long a,
                                                   unsigned long long b,
                                                   unsigned long long c) {
    unsigned long long d;
    asm("fma.rn.f32x2 %0, %1, %2, %3;" : "=l"(d) : "l"(a), "l"(b), "l"(c));
    return d;
}

// =====================================================================
// prep_w: transpose W1/W2 to [N,K] K-major, split into bf16 hi/lo
// =====================================================================
__global__ void prep_w(const float* __restrict__ W1, const float* __restrict__ W2,
                       __nv_bfloat16* __restrict__ w1h, __nv_bfloat16* __restrict__ w1l,
                       __nv_bfloat16* __restrict__ w2h, __nv_bfloat16* __restrict__ w2l) {
    const int n = blockIdx.x, k = threadIdx.x;
    float v1 = W1[k * 256 + n];
    __nv_bfloat16 h1 = __float2bfloat16_rn(v1);
    w1h[n * 256 + k] = h1;
    w1l[n * 256 + k] = __float2bfloat16_rn(v1 - __bfloat162float(h1));
    float v2 = W2[k * 256 + n];
    __nv_bfloat16 h2 = __float2bfloat16_rn(v2);
    w2h[n * 256 + k] = h2;
    w2l[n * 256 + k] = __float2bfloat16_rn(v2 - __bfloat162float(h2));
}

// =====================================================================
// k_prep: adj = mean(graph, bands); y1 = adj @ x -> bf16 hi/lo split
// (proven R3 kernel, unchanged)
// =====================================================================
__global__ __launch_bounds__(128)
void k_prep(const float* __restrict__ graph, const float* __restrict__ x,
            float* __restrict__ adj_out,
            __nv_bfloat16* __restrict__ ah, __nv_bfloat16* __restrict__ al) {
    __shared__ float adj_s[900];
    const int tid = threadIdx.x;
    const size_t b = blockIdx.x;

    const float* gp = graph + b * 4500;
    float* ao = adj_out + b * 900;
    for (int e = tid; e < 900; e += 128) {
        float s = 0.2f * (gp[e] + gp[e + 900] + gp[e + 1800] + gp[e + 2700] + gp[e + 3600]);
        adj_s[e] = s;
        ao[e] = s;
    }

    const int j = tid * 2;
    const float* xp = x + b * 7680 + j;
    unsigned long long xr[30];
    #pragma unroll
    for (int k = 0; k < 30; ++k) {
        float2 v = *(const float2*)(xp + (size_t)k * 256);
        xr[k] = pk2(v.x, v.y);
    }
    __syncthreads();

    #pragma unroll 1
    for (int i = 0; i < 30; ++i) {
        unsigned long long acc = 0ULL;
        const float* ar = adj_s + i * 30;
        #pragma unroll
        for (int k = 0; k < 30; ++k) {
            float a = ar[k];
            acc = fma2(pk2(a, a), xr[k], acc);
        }
        float y0, y1;
        upk2(acc, y0, y1);
        __nv_bfloat16 h0 = __float2bfloat16_rn(y0);
        __nv_bfloat16 h1 = __float2bfloat16_rn(y1);
        __nv_bfloat162 hv, lv;
        hv.x = h0; hv.y = h1;
        lv.x = __float2bfloat16_rn(y0 - __bfloat162float(h0));
        lv.y = __float2bfloat16_rn(y1 - __bfloat162float(h1));
        size_t ro = (b * 30 + i) * 256 + j;
        *(__nv_bfloat162*)(ah + ro) = hv;
        *(__nv_bfloat162*)(al + ro) = lv;
    }
}

// =====================================================================
// GEMM: C[64,256] = A[64,256] @ W[256,256]^T(K-major), split-bf16 3-pass.
// A (hi+lo, 64KB) resident in smem; W double-buffered KC=16 stages.
// 256 threads, 8 warps (2 warp_m x 4 warp_n), warp tile 32x64, 2 CTAs/SM.
// MODE 1: write relu(C+bias) as bf16 hi/lo split (-> g_hh/g_hl)
// MODE 2: write C as fp32 (-> g_u2)
// smem: A hi [0,32768) as 4 chunks [64x128B] SW128; A lo [32768,65536)
//       W stages [65536, 65536+2*16384): per stage hi 8KB + lo 8KB,
//         packed [64 rows x 128B]: row r holds n=r,r+64,r+128,r+192 (32B each)
//       bias [98304, 99328)
// =====================================================================
#define GSM_A    0u
#define GSM_W    65536u
#define GSM_BIAS 98304u
#define GSM_TOTAL 99328

template <int MODE>
__global__ __launch_bounds__(256, 2)
void gemm_hmma(const __nv_bfloat16* __restrict__ Ah, const __nv_bfloat16* __restrict__ Al,
               const __nv_bfloat16* __restrict__ Wh, const __nv_bfloat16* __restrict__ Wl,
               const float* __restrict__ bias,
               __nv_bfloat16* __restrict__ OutH, __nv_bfloat16* __restrict__ OutL,
               float* __restrict__ OutF) {
    extern __shared__ char smem[];
    const uint32_t sb = smem_to_u32(smem);
    const int tid = threadIdx.x, lane = tid & 31, wid = tid >> 5;
    const int warp_m = wid & 1, warp_n = wid >> 1;
    const size_t arow0 = (size_t)blockIdx.x * 64;

    // ---- A resident load (hi+lo, 64KB) ----
    {
        const __nv_bfloat16* gA = Ah + arow0 * 256;
        const __nv_bfloat16* gL = Al + arow0 * 256;
        #pragma unroll
        for (int u = tid; u < 2048; u += 256) {
            int row = u >> 5, s = u & 31;
            int c = s >> 3, ss = s & 7;
            uint32_t off = (uint32_t)c * 8192u + (uint32_t)(row * 128)
                         + (((uint32_t)ss * 16u) ^ ((uint32_t)(row & 7) << 4));
            size_t go = (size_t)row * 256 + s * 8;
            cpasync16(sb + GSM_A + off,           gA + go);
            cpasync16(sb + GSM_A + 32768u + off,  gL + go);
        }
        asm volatile("cp.async.commit_group;" ::: "memory");
    }
    if (MODE == 1) ((float*)(smem + GSM_BIAS))[tid] = bias[tid];

    // ---- W stage loader: chunk kc covers k [kc*16, kc*16+16) ----
    auto wload = [&](int kc) {
        uint32_t st = sb + GSM_W + (uint32_t)(kc & 1) * 16384u;
        #pragma unroll
        for (int u = tid; u < 1024; u += 256) {
            int arr = u >> 9, v = u & 511;       // 512 x 16B per array
            int n = v >> 1, half = v & 1;
            int row = n & 63, sub = n >> 6;
            uint32_t off = (uint32_t)(row * 128)
                         + (((uint32_t)(sub * 32 + half * 16)) ^ ((uint32_t)(row & 7) << 4));
            size_t go = (size_t)n * 256 + (size_t)kc * 16 + half * 8;
            cpasync16(st + (uint32_t)arr * 8192u + off, (arr ? Wl : Wh) + go);
        }
        asm volatile("cp.async.commit_group;" ::: "memory");
    };
    wload(0);
    wload(1);

    // ---- ldmatrix addressing ----
    const int matv = lane >> 3;
    const int rA0 = warp_m * 32 + (matv & 1) * 8 + (lane & 7);
    const int kAoff = (matv >> 1) * 16;
    const int nB0 = warp_n * 64 + matv * 8 + (lane & 7);
    const uint32_t xorv = (uint32_t)((lane & 7) << 4);

    float acc[2][8][4];
    #pragma unroll
    for (int m = 0; m < 2; ++m)
        #pragma unroll
        for (int j = 0; j < 8; ++j)
            #pragma unroll
            for (int q = 0; q < 4; ++q) acc[m][j][q] = 0.f;

    #pragma unroll 1
    for (int kc = 0; kc < 16; ++kc) {
        if (kc < 15) asm volatile("cp.async.wait_group 1;" ::: "memory");
        else         asm volatile("cp.async.wait_group 0;" ::: "memory");
        __syncthreads();

        const uint32_t wst = sb + GSM_W + (uint32_t)(kc & 1) * 16384u;
        const uint32_t abase = sb + GSM_A + (uint32_t)(kc >> 2) * 8192u;
        const uint32_t aco = ((uint32_t)((kc & 3) * 32 + kAoff)) ^ xorv;

        uint32_t ah_f[2][4], al_f[2][4];
        #pragma unroll
        for (int mt = 0; mt < 2; ++mt) {
            uint32_t ro = (uint32_t)((rA0 + mt * 16) * 128);
            ldsm4(ah_f[mt], abase + ro + aco);
            ldsm4(al_f[mt], abase + 32768u + ro + aco);
        }
        #pragma unroll
        for (int jb = 0; jb < 2; ++jb) {
            const int n = nB0 + jb * 32;
            const uint32_t ro = (uint32_t)((n & 63) * 128);
            const uint32_t base = (uint32_t)((n >> 6) * 32);
            const uint32_t c0 = (base)       ^ xorv;
            const uint32_t c1 = (base + 16u) ^ xorv;
            uint32_t bh0[4], bh1[4], bl0[4], bl1[4];
            ldsm4(bh0, wst + ro + c0);
            ldsm4(bh1, wst + ro + c1);
            ldsm4(bl0, wst + 8192u + ro + c0);
            ldsm4(bl1, wst + 8192u + ro + c1);
            #pragma unroll
            for (int mt = 0; mt < 2; ++mt)
                #pragma unroll
                for (int jj = 0; jj < 4; ++jj) {
                    int j = jb * 4 + jj;
                    mma_bf16(acc[mt][j], ah_f[mt], bh0[jj], bh1[jj]);
                    mma_bf16(acc[mt][j], ah_f[mt], bl0[jj], bl1[jj]);
                    mma_bf16(acc[mt][j], al_f[mt], bh0[jj], bh1[jj]);
                }
        }
        __syncthreads();
        if (kc + 2 < 16) wload(kc + 2);
    }

    // ---- epilogue ----
    const int g = lane >> 2, cq = (lane & 3) * 2;
    #pragma unroll
    for (int mt = 0; mt < 2; ++mt) {
        const size_t r0 = arow0 + warp_m * 32 + mt * 16 + g;
        #pragma unroll
        for (int j = 0; j < 8; ++j) {
            const int col = warp_n * 64 + j * 8 + cq;
            if (MODE == 1) {
                const float* b1s = (const float*)(smem + GSM_BIAS);
                float bb0 = b1s[col], bb1 = b1s[col + 1];
                #pragma unroll
                for (int half = 0; half < 2; ++half) {
                    size_t R = r0 + half * 8;
                    float v0 = fmaxf(acc[mt][j][half * 2]     + bb0, 0.f);
                    float v1 = fmaxf(acc[mt][j][half * 2 + 1] + bb1, 0.f);
                    __nv_bfloat16 h0 = __float2bfloat16_rn(v0), h1 = __float2bfloat16_rn(v1);
                    __nv_bfloat162 hv; hv.x = h0; hv.y = h1;
                    __nv_bfloat162 lv;
                    lv.x = __float2bfloat16_rn(v0 - __bfloat162float(h0));
                    lv.y = __float2bfloat16_rn(v1 - __bfloat162float(h1));
                    *(__nv_bfloat162*)(OutH + R * 256 + col) = hv;
                    *(__nv_bfloat162*)(OutL + R * 256 + col) = lv;
                }
            } else {
                *(float2*)(OutF + r0 * 256 + col)       = make_float2(acc[mt][j][0], acc[mt][j][1]);
                *(float2*)(OutF + (r0 + 8) * 256 + col) = make_float2(acc[mt][j][2], acc[mt][j][3]);
            }
        }
    }
}

// =====================================================================
// k_final: per batch: g2 = adj @ u2; p = relu(g2+b2) . wlin;
//          xl = relu(p + blin); out = xl @ W_head^T + b_head
// 4 batches per 512-thread CTA; 128 threads per batch own 2 cols each.
// =====================================================================
__global__ __launch_bounds__(512)
void k_final(const float* __restrict__ adj, const float* __restrict__ u2,
             const float* __restrict__ b2g, const float* __restrict__ wling,
             const float* __restrict__ bling, const float* __restrict__ Wheadg,
             const float* __restrict__ bheadg, float* __restrict__ out) {
    __shared__ float adj_s[4 * 960];
    __shared__ float red[4][30][4];
    const int tid = threadIdx.x;
    const int b = tid >> 7, t2 = tid & 127, w = t2 >> 5;
    const size_t b0 = (size_t)blockIdx.x * 4;

    for (int e = tid; e < 3600; e += 512) {
        int bb = e / 900, i = e - bb * 900;
        adj_s[bb * 960 + (i / 30) * 32 + (i % 30)] = adj[(b0 + bb) * 900 + i];
    }

    const int j = t2 * 2;
    const float* up = u2 + (b0 + b) * 7680 + j;
    unsigned long long uk[30];
    #pragma unroll
    for (int k = 0; k < 30; ++k) {
        float2 v = *(const float2*)(up + (size_t)k * 256);
        uk[k] = pk2(v.x, v.y);
    }
    const float b2v0 = __ldg(b2g + j), b2v1 = __ldg(b2g + j + 1);
    const float wl0 = __ldg(wling + j), wl1 = __ldg(wling + j + 1);
    __syncthreads();

    const float* ar = adj_s + b * 960;
    #pragma unroll 1
    for (int i = 0; i < 30; ++i) {
        unsigned long long acc = 0ULL;
        #pragma unroll
        for (int k = 0; k < 30; ++k) {
            float a = ar[i * 32 + k];
            acc = fma2(pk2(a, a), uk[k], acc);
        }
        float s0, s1;
        upk2(acc, s0, s1);
        float p = fmaxf(s0 + b2v0, 0.f) * wl0 + fmaxf(s1 + b2v1, 0.f) * wl1;
        #pragma unroll
        for (int o = 16; o > 0; o >>= 1) p += __shfl_xor_sync(0xffffffffu, p, o);
        if ((t2 & 31) == 0) red[b][i][w] = p;
    }
    __syncthreads();

    if (tid < 36) {
        const int bb = tid / 9, c = tid - bb * 9;
        const float bl = __ldg(bling);
        float s = __ldg(bheadg + c);
        #pragma unroll
        for (int i = 0; i < 30; ++i) {
            float xl = fmaxf(red[bb][i][0] + red[bb][i][1] + red[bb][i][2] + red[bb][i][3] + bl, 0.f);
            s = fmaf(xl, __ldg(Wheadg + c * 30 + i), s);
        }
        out[(b0 + bb) * 9 + c] = s;
    }
}

// =====================================================================
extern "C" void kernel_launch(void* const* d_in, const int* in_sizes, int n_in,
                              void* d_out, int out_size) {
    const float* real  = (const float*)d_in[0];
    const float* graph = (const float*)d_in[2];
    const float* W1    = (const float*)d_in[3];
    const float* b1    = (const float*)d_in[4];
    const float* W2    = (const float*)d_in[5];
    const float* b2    = (const float*)d_in[6];
    const float* wlin  = (const float*)d_in[7];
    const float* blin  = (const float*)d_in[8];
    const float* Whead = (const float*)d_in[9];
    const float* bhead = (const float*)d_in[10];
    float* out = (float*)d_out;

    float *adj_p, *u2_p;
    __nv_bfloat16 *ah_p, *al_p, *hh_p, *hl_p, *w1h_p, *w1l_p, *w2h_p, *w2l_p;
    cudaGetSymbolAddress((void**)&adj_p, g_adj);
    cudaGetSymbolAddress((void**)&u2_p,  g_u2);
    cudaGetSymbolAddress((void**)&ah_p,  g_ah);
    cudaGetSymbolAddress((void**)&al_p,  g_al);
    cudaGetSymbolAddress((void**)&hh_p,  g_hh);
    cudaGetSymbolAddress((void**)&hl_p,  g_hl);
    cudaGetSymbolAddress((void**)&w1h_p, g_w1h);
    cudaGetSymbolAddress((void**)&w1l_p, g_w1l);
    cudaGetSymbolAddress((void**)&w2h_p, g_w2h);
    cudaGetSymbolAddress((void**)&w2l_p, g_w2l);

    cudaFuncSetAttribute(gemm_hmma<1>, cudaFuncAttributeMaxDynamicSharedMemorySize, GSM_TOTAL);
    cudaFuncSetAttribute(gemm_hmma<2>, cudaFuncAttributeMaxDynamicSharedMemorySize, GSM_TOTAL);

    // 1. weight transpose + bf16 split
    prep_w<<<256, 256>>>(W1, W2, w1h_p, w1l_p, w2h_p, w2l_p);
    // 2. adj = mean(graph); y1 = adj @ real (bf16 hi/lo)
    k_prep<<<BATCH, 128>>>(graph, real, adj_p, ah_p, al_p);
    // 3. h1 = relu(y1 @ W1 + b1) -> bf16 hi/lo split (fused epilogue)
    gemm_hmma<1><<<MROWS / 64, 256, GSM_TOTAL>>>(ah_p, al_p, w1h_p, w1l_p, b1,
                                                 hh_p, hl_p, nullptr);
    // 4. u2 = h1 @ W2 (fp32)   [re-association: adj@(h1@W2) == (adj@h1)@W2]
    gemm_hmma<2><<<MROWS / 64, 256, GSM_TOTAL>>>(hh_p, hl_p, w2h_p, w2l_p, nullptr,
                                                 nullptr, nullptr, u2_p);
    // 5. fused: g2 = adj@u2; relu(+b2) . wlin; relu(+blin); head -> out
    k_final<<<BATCH / 4, 512>>>(adj_p, u2_p, b2, wlin, blin, Whead, bhead, out);
}

// round 8
// speedup vs baseline: 1.0991x; 1.0171x over previous
#include <cuda_runtime.h>
#include <cuda_bf16.h>
#include <cuda_fp16.h>
#include <cstdint>

#define BATCH 8192
#define NNODE 30
#define FEAT  256
#define MROWS (BATCH * NNODE)   // 245760

// ---------------- scratch (device globals) ----------------
__device__ float         g_adj[(size_t)BATCH * NNODE * NNODE];  // 29.5 MB
__device__ __nv_bfloat16 g_ah[(size_t)MROWS * FEAT];            // y1 split hi
__device__ __nv_bfloat16 g_al[(size_t)MROWS * FEAT];            // y1 split lo
__device__ __nv_bfloat16 g_hh[(size_t)MROWS * FEAT];            // h1 split hi
__device__ __nv_bfloat16 g_hl[(size_t)MROWS * FEAT];            // h1 split lo
__device__ __half        g_u2[(size_t)MROWS * FEAT];            // u2 fp16
__device__ __nv_bfloat16 g_w1h[FEAT * FEAT], g_w1l[FEAT * FEAT];
__device__ __nv_bfloat16 g_w2h[FEAT * FEAT], g_w2l[FEAT * FEAT];

// ==================== helpers ====================
__device__ __forceinline__ uint32_t smem_to_u32(const void* p) {
    uint32_t a;
    asm("{ .reg .u64 t; cvta.to.shared.u64 t, %1; cvt.u32.u64 %0, t; }" : "=r"(a) : "l"(p));
    return a;
}
__device__ __forceinline__ void cpasync16(uint32_t saddr, const void* g) {
    asm volatile("cp.async.cg.shared.global [%0], [%1], 16;" :: "r"(saddr), "l"(g));
}
__device__ __forceinline__ void ldsm4(uint32_t* r, uint32_t addr) {
    asm volatile("ldmatrix.sync.aligned.m8n8.x4.shared.b16 {%0,%1,%2,%3}, [%4];"
        : "=r"(r[0]), "=r"(r[1]), "=r"(r[2]), "=r"(r[3]) : "r"(addr));
}
__device__ __forceinline__ void mma_bf16(float* d, const uint32_t* a, uint32_t b0, uint32_t b1) {
    asm volatile(
        "mma.sync.aligned.m16n8k16.row.col.f32.bf16.bf16.f32 "
        "{%0,%1,%2,%3}, {%4,%5,%6,%7}, {%8,%9}, {%0,%1,%2,%3};"
        : "+f"(d[0]), "+f"(d[1]), "+f"(d[2]), "+f"(d[3])
        : "r"(a[0]), "r"(a[1]), "r"(a[2]), "r"(a[3]), "r"(b0), "r"(b1));
}
__device__ __forceinline__ unsigned long long pk2(float x, float y) {
    unsigned long long r;
    asm("mov.b64 %0, {%1, %2};" : "=l"(r) : "f"(x), "f"(y));
    return r;
}
__device__ __forceinline__ void upk2(unsigned long long v, float& x, float& y) {
    asm("mov.b64 {%0, %1}, %2;" : "=f"(x), "=f"(y) : "l"(v));
}
__device__ __forceinline__ unsigned long long fma2(unsigned long long a,
                                                   unsigned long long b,
                                                   unsigned long long c) {
    unsigned long long d;
    asm("fma.rn.f32x2 %0, %1, %2, %3;" : "=l"(d) : "l"(a), "l"(b), "l"(c));
    return d;
}

// =====================================================================
// prep_w: transpose W1/W2 to [N,K] K-major, split into bf16 hi/lo
// =====================================================================
__global__ void prep_w(const float* __restrict__ W1, const float* __restrict__ W2,
                       __nv_bfloat16* __restrict__ w1h, __nv_bfloat16* __restrict__ w1l,
                       __nv_bfloat16* __restrict__ w2h, __nv_bfloat16* __restrict__ w2l) {
    const int n = blockIdx.x, k = threadIdx.x;
    float v1 = W1[k * 256 + n];
    __nv_bfloat16 h1 = __float2bfloat16_rn(v1);
    w1h[n * 256 + k] = h1;
    w1l[n * 256 + k] = __float2bfloat16_rn(v1 - __bfloat162float(h1));
    float v2 = W2[k * 256 + n];
    __nv_bfloat16 h2 = __float2bfloat16_rn(v2);
    w2h[n * 256 + k] = h2;
    w2l[n * 256 + k] = __float2bfloat16_rn(v2 - __bfloat162float(h2));
}

// =====================================================================
// k_prep: adj = mean(graph, bands); y1 = adj @ x -> bf16 hi/lo split
// =====================================================================
__global__ __launch_bounds__(128)
void k_prep(const float* __restrict__ graph, const float* __restrict__ x,
            float* __restrict__ adj_out,
            __nv_bfloat16* __restrict__ ah, __nv_bfloat16* __restrict__ al) {
    __shared__ float adj_s[900];
    const int tid = threadIdx.x;
    const size_t b = blockIdx.x;

    const float* gp = graph + b * 4500;
    float* ao = adj_out + b * 900;
    for (int e = tid; e < 900; e += 128) {
        float s = 0.2f * (gp[e] + gp[e + 900] + gp[e + 1800] + gp[e + 2700] + gp[e + 3600]);
        adj_s[e] = s;
        ao[e] = s;
    }

    const int j = tid * 2;
    const float* xp = x + b * 7680 + j;
    unsigned long long xr[30];
    #pragma unroll
    for (int k = 0; k < 30; ++k) {
        float2 v = *(const float2*)(xp + (size_t)k * 256);
        xr[k] = pk2(v.x, v.y);
    }
    __syncthreads();

    #pragma unroll 1
    for (int i = 0; i < 30; ++i) {
        unsigned long long acc = 0ULL;
        const float* ar = adj_s + i * 30;
        #pragma unroll
        for (int k = 0; k < 30; ++k) {
            float a = ar[k];
            acc = fma2(pk2(a, a), xr[k], acc);
        }
        float y0, y1;
        upk2(acc, y0, y1);
        __nv_bfloat16 h0 = __float2bfloat16_rn(y0);
        __nv_bfloat16 h1 = __float2bfloat16_rn(y1);
        __nv_bfloat162 hv, lv;
        hv.x = h0; hv.y = h1;
        lv.x = __float2bfloat16_rn(y0 - __bfloat162float(h0));
        lv.y = __float2bfloat16_rn(y1 - __bfloat162float(h1));
        size_t ro = (b * 30 + i) * 256 + j;
        *(__nv_bfloat162*)(ah + ro) = hv;
        *(__nv_bfloat162*)(al + ro) = lv;
    }
}

// =====================================================================
// GEMM: C[64,256] = A[64,256] @ W[256,256]^T(K-major), split-bf16 3-pass.
// A resident (64KB); W double-buffered KC=16, DEPTH-1 PREFETCH:
// one __syncthreads per chunk; wload(kc+1) overlaps chunk kc math.
// MODE 1: Out = relu(C+bias) -> bf16 hi/lo split
// MODE 2: Out = C -> fp16
// =====================================================================
#define GSM_A    0u
#define GSM_W    65536u
#define GSM_BIAS 98304u
#define GSM_TOTAL 99328

template <int MODE>
__global__ __launch_bounds__(256, 2)
void gemm_hmma(const __nv_bfloat16* __restrict__ Ah, const __nv_bfloat16* __restrict__ Al,
               const __nv_bfloat16* __restrict__ Wh, const __nv_bfloat16* __restrict__ Wl,
               const float* __restrict__ bias,
               __nv_bfloat16* __restrict__ OutH, __nv_bfloat16* __restrict__ OutL,
               __half* __restrict__ OutF) {
    extern __shared__ char smem[];
    const uint32_t sb = smem_to_u32(smem);
    const int tid = threadIdx.x, lane = tid & 31, wid = tid >> 5;
    const int warp_m = wid & 1, warp_n = wid >> 1;
    const size_t arow0 = (size_t)blockIdx.x * 64;

    // ---- A resident load (hi+lo, 64KB), one commit group ----
    {
        const __nv_bfloat16* gA = Ah + arow0 * 256;
        const __nv_bfloat16* gL = Al + arow0 * 256;
        #pragma unroll
        for (int u = tid; u < 2048; u += 256) {
            int row = u >> 5, s = u & 31;
            int c = s >> 3, ss = s & 7;
            uint32_t off = (uint32_t)c * 8192u + (uint32_t)(row * 128)
                         + (((uint32_t)ss * 16u) ^ ((uint32_t)(row & 7) << 4));
            size_t go = (size_t)row * 256 + s * 8;
            cpasync16(sb + GSM_A + off,           gA + go);
            cpasync16(sb + GSM_A + 32768u + off,  gL + go);
        }
        asm volatile("cp.async.commit_group;" ::: "memory");
    }
    if (MODE == 1) ((float*)(smem + GSM_BIAS))[tid] = bias[tid];

    // ---- W stage loader: chunk kc covers k [kc*16, kc*16+16) ----
    auto wload = [&](int kc) {
        uint32_t st = sb + GSM_W + (uint32_t)(kc & 1) * 16384u;
        #pragma unroll
        for (int u = tid; u < 1024; u += 256) {
            int arr = u >> 9, v = u & 511;
            int n = v >> 1, half = v & 1;
            int row = n & 63, sub = n >> 6;
            uint32_t off = (uint32_t)(row * 128)
                         + (((uint32_t)(sub * 32 + half * 16)) ^ ((uint32_t)(row & 7) << 4));
            size_t go = (size_t)n * 256 + (size_t)kc * 16 + half * 8;
            cpasync16(st + (uint32_t)arr * 8192u + off, (arr ? Wl : Wh) + go);
        }
        asm volatile("cp.async.commit_group;" ::: "memory");
    };
    wload(0);

    // ---- ldmatrix addressing ----
    const int matv = lane >> 3;
    const int rA0 = warp_m * 32 + (matv & 1) * 8 + (lane & 7);
    const int kAoff = (matv >> 1) * 16;
    const int nB0 = warp_n * 64 + matv * 8 + (lane & 7);
    const uint32_t xorv = (uint32_t)((lane & 7) << 4);

    float acc[2][8][4];
    #pragma unroll
    for (int m = 0; m < 2; ++m)
        #pragma unroll
        for (int j = 0; j < 8; ++j)
            #pragma unroll
            for (int q = 0; q < 4; ++q) acc[m][j][q] = 0.f;

    #pragma unroll 1
    for (int kc = 0; kc < 16; ++kc) {
        asm volatile("cp.async.wait_group 0;" ::: "memory");
        __syncthreads();
        // depth-1 prefetch: writes the OTHER stage -> no hazard, overlaps math
        if (kc + 1 < 16) wload(kc + 1);

        const uint32_t wst = sb + GSM_W + (uint32_t)(kc & 1) * 16384u;
        const uint32_t abase = sb + GSM_A + (uint32_t)(kc >> 2) * 8192u;
        const uint32_t aco = ((uint32_t)((kc & 3) * 32 + kAoff)) ^ xorv;

        uint32_t ah_f[2][4], al_f[2][4];
        #pragma unroll
        for (int mt = 0; mt < 2; ++mt) {
            uint32_t ro = (uint32_t)((rA0 + mt * 16) * 128);
            ldsm4(ah_f[mt], abase + ro + aco);
            ldsm4(al_f[mt], abase + 32768u + ro + aco);
        }
        #pragma unroll
        for (int jb = 0; jb < 2; ++jb) {
            const int n = nB0 + jb * 32;
            const uint32_t ro = (uint32_t)((n & 63) * 128);
            const uint32_t base = (uint32_t)((n >> 6) * 32);
            const uint32_t c0 = (base)       ^ xorv;
            const uint32_t c1 = (base + 16u) ^ xorv;
            uint32_t bh0[4], bh1[4], bl0[4], bl1[4];
            ldsm4(bh0, wst + ro + c0);
            ldsm4(bh1, wst + ro + c1);
            ldsm4(bl0, wst + 8192u + ro + c0);
            ldsm4(bl1, wst + 8192u + ro + c1);
            #pragma unroll
            for (int mt = 0; mt < 2; ++mt)
                #pragma unroll
                for (int jj = 0; jj < 4; ++jj) {
                    int j = jb * 4 + jj;
                    mma_bf16(acc[mt][j], ah_f[mt], bh0[jj], bh1[jj]);
                    mma_bf16(acc[mt][j], ah_f[mt], bl0[jj], bl1[jj]);
                    mma_bf16(acc[mt][j], al_f[mt], bh0[jj], bh1[jj]);
                }
        }
        // no second barrier: next iteration's sync protects stage reuse
    }

    // ---- epilogue ----
    const int g = lane >> 2, cq = (lane & 3) * 2;
    #pragma unroll
    for (int mt = 0; mt < 2; ++mt) {
        const size_t r0 = arow0 + warp_m * 32 + mt * 16 + g;
        #pragma unroll
        for (int j = 0; j < 8; ++j) {
            const int col = warp_n * 64 + j * 8 + cq;
            if (MODE == 1) {
                const float* b1s = (const float*)(smem + GSM_BIAS);
                float bb0 = b1s[col], bb1 = b1s[col + 1];
                #pragma unroll
                for (int half = 0; half < 2; ++half) {
                    size_t R = r0 + half * 8;
                    float v0 = fmaxf(acc[mt][j][half * 2]     + bb0, 0.f);
                    float v1 = fmaxf(acc[mt][j][half * 2 + 1] + bb1, 0.f);
                    __nv_bfloat16 h0 = __float2bfloat16_rn(v0), h1 = __float2bfloat16_rn(v1);
                    __nv_bfloat162 hv; hv.x = h0; hv.y = h1;
                    __nv_bfloat162 lv;
                    lv.x = __float2bfloat16_rn(v0 - __bfloat162float(h0));
                    lv.y = __float2bfloat16_rn(v1 - __bfloat162float(h1));
                    *(__nv_bfloat162*)(OutH + R * 256 + col) = hv;
                    *(__nv_bfloat162*)(OutL + R * 256 + col) = lv;
                }
            } else {
                *(__half2*)(OutF + r0 * 256 + col) =
                    __floats2half2_rn(acc[mt][j][0], acc[mt][j][1]);
                *(__half2*)(OutF + (r0 + 8) * 256 + col) =
                    __floats2half2_rn(acc[mt][j][2], acc[mt][j][3]);
            }
        }
    }
}

// =====================================================================
// k_final: g2 = adj @ u2; p = relu(g2+b2).wlin; xl = relu(p+blin);
//          out = xl @ W_head^T + b_head.  u2 in fp16.
// =====================================================================
__global__ __launch_bounds__(512)
void k_final(const float* __restrict__ adj, const __half* __restrict__ u2,
             const float* __restrict__ b2g, const float* __restrict__ wling,
             const float* __restrict__ bling, const float* __restrict__ Wheadg,
             const float* __restrict__ bheadg, float* __restrict__ out) {
    __shared__ float adj_s[4 * 960];
    __shared__ float red[4][30][4];
    const int tid = threadIdx.x;
    const int b = tid >> 7, t2 = tid & 127, w = t2 >> 5;
    const size_t b0 = (size_t)blockIdx.x * 4;

    for (int e = tid; e < 3600; e += 512) {
        int bb = e / 900, i = e - bb * 900;
        adj_s[bb * 960 + (i / 30) * 32 + (i % 30)] = adj[(b0 + bb) * 900 + i];
    }

    const int j = t2 * 2;
    const __half* up = u2 + (b0 + b) * 7680 + j;
    unsigned long long uk[30];
    #pragma unroll
    for (int k = 0; k < 30; ++k) {
        float2 v = __half22float2(*(const __half2*)(up + (size_t)k * 256));
        uk[k] = pk2(v.x, v.y);
    }
    const float b2v0 = __ldg(b2g + j), b2v1 = __ldg(b2g + j + 1);
    const float wl0 = __ldg(wling + j), wl1 = __ldg(wling + j + 1);
    __syncthreads();

    const float* ar = adj_s + b * 960;
    #pragma unroll 1
    for (int i = 0; i < 30; ++i) {
        unsigned long long acc = 0ULL;
        #pragma unroll
        for (int k = 0; k < 30; ++k) {
            float a = ar[i * 32 + k];
            acc = fma2(pk2(a, a), uk[k], acc);
        }
        float s0, s1;
        upk2(acc, s0, s1);
        float p = fmaxf(s0 + b2v0, 0.f) * wl0 + fmaxf(s1 + b2v1, 0.f) * wl1;
        #pragma unroll
        for (int o = 16; o > 0; o >>= 1) p += __shfl_xor_sync(0xffffffffu, p, o);
        if ((t2 & 31) == 0) red[b][i][w] = p;
    }
    __syncthreads();

    if (tid < 36) {
        const int bb = tid / 9, c = tid - bb * 9;
        const float bl = __ldg(bling);
        float s = __ldg(bheadg + c);
        #pragma unroll
        for (int i = 0; i < 30; ++i) {
            float xl = fmaxf(red[bb][i][0] + red[bb][i][1] + red[bb][i][2] + red[bb][i][3] + bl, 0.f);
            s = fmaf(xl, __ldg(Wheadg + c * 30 + i), s);
        }
        out[(b0 + bb) * 9 + c] = s;
    }
}

// =====================================================================
extern "C" void kernel_launch(void* const* d_in, const int* in_sizes, int n_in,
                              void* d_out, int out_size) {
    const float* real  = (const float*)d_in[0];
    const float* graph = (const float*)d_in[2];
    const float* W1    = (const float*)d_in[3];
    const float* b1    = (const float*)d_in[4];
    const float* W2    = (const float*)d_in[5];
    const float* b2    = (const float*)d_in[6];
    const float* wlin  = (const float*)d_in[7];
    const float* blin  = (const float*)d_in[8];
    const float* Whead = (const float*)d_in[9];
    const float* bhead = (const float*)d_in[10];
    float* out = (float*)d_out;

    float *adj_p;
    __half *u2_p;
    __nv_bfloat16 *ah_p, *al_p, *hh_p, *hl_p, *w1h_p, *w1l_p, *w2h_p, *w2l_p;
    cudaGetSymbolAddress((void**)&adj_p, g_adj);
    cudaGetSymbolAddress((void**)&u2_p,  g_u2);
    cudaGetSymbolAddress((void**)&ah_p,  g_ah);
    cudaGetSymbolAddress((void**)&al_p,  g_al);
    cudaGetSymbolAddress((void**)&hh_p,  g_hh);
    cudaGetSymbolAddress((void**)&hl_p,  g_hl);
    cudaGetSymbolAddress((void**)&w1h_p, g_w1h);
    cudaGetSymbolAddress((void**)&w1l_p, g_w1l);
    cudaGetSymbolAddress((void**)&w2h_p, g_w2h);
    cudaGetSymbolAddress((void**)&w2l_p, g_w2l);

    cudaFuncSetAttribute(gemm_hmma<1>, cudaFuncAttributeMaxDynamicSharedMemorySize, GSM_TOTAL);
    cudaFuncSetAttribute(gemm_hmma<2>, cudaFuncAttributeMaxDynamicSharedMemorySize, GSM_TOTAL);

    // 1. weight transpose + bf16 split
    prep_w<<<256, 256>>>(W1, W2, w1h_p, w1l_p, w2h_p, w2l_p);
    // 2. adj = mean(graph); y1 = adj @ real (bf16 hi/lo)
    k_prep<<<BATCH, 128>>>(graph, real, adj_p, ah_p, al_p);
    // 3. h1 = relu(y1 @ W1 + b1) -> bf16 hi/lo split
    gemm_hmma<1><<<MROWS / 64, 256, GSM_TOTAL>>>(ah_p, al_p, w1h_p, w1l_p, b1,
                                                 hh_p, hl_p, nullptr);
    // 4. u2 = h1 @ W2 (fp16)
    gemm_hmma<2><<<MROWS / 64, 256, GSM_TOTAL>>>(hh_p, hl_p, w2h_p, w2l_p, nullptr,
                                                 nullptr, nullptr, u2_p);
    // 5. fused: g2 = adj@u2; relu(+b2).wlin; relu(+blin); head -> out
    k_final<<<BATCH / 4, 512>>>(adj_p, u2_p, b2, wlin, blin, Whead, bhead, out);
}

// round 9
// speedup vs baseline: 1.7394x; 1.5825x over previous
#include <cuda_runtime.h>
#include <cuda_fp16.h>
#include <cstdint>

#define BATCH 8192
#define NNODE 30
#define FEAT  256
#define MROWS (BATCH * NNODE)   // 245760

// ---------------- scratch (device globals) ----------------
__device__ float  g_adj[(size_t)BATCH * NNODE * NNODE];  // 29.5 MB
__device__ __half g_y1[(size_t)MROWS * FEAT];            // 125 MB
__device__ __half g_h1[(size_t)MROWS * FEAT];            // 125 MB
__device__ __half g_u2[(size_t)MROWS * FEAT];            // 125 MB
__device__ __half g_w1[FEAT * FEAT], g_w2[FEAT * FEAT];

// ==================== helpers ====================
__device__ __forceinline__ uint32_t smem_to_u32(const void* p) {
    uint32_t a;
    asm("{ .reg .u64 t; cvta.to.shared.u64 t, %1; cvt.u32.u64 %0, t; }" : "=r"(a) : "l"(p));
    return a;
}
__device__ __forceinline__ void cpasync16(uint32_t saddr, const void* g) {
    asm volatile("cp.async.cg.shared.global [%0], [%1], 16;" :: "r"(saddr), "l"(g));
}
__device__ __forceinline__ void ldsm4(uint32_t* r, uint32_t addr) {
    asm volatile("ldmatrix.sync.aligned.m8n8.x4.shared.b16 {%0,%1,%2,%3}, [%4];"
        : "=r"(r[0]), "=r"(r[1]), "=r"(r[2]), "=r"(r[3]) : "r"(addr));
}
__device__ __forceinline__ void mma_f16(float* d, const uint32_t* a, uint32_t b0, uint32_t b1) {
    asm volatile(
        "mma.sync.aligned.m16n8k16.row.col.f32.f16.f16.f32 "
        "{%0,%1,%2,%3}, {%4,%5,%6,%7}, {%8,%9}, {%0,%1,%2,%3};"
        : "+f"(d[0]), "+f"(d[1]), "+f"(d[2]), "+f"(d[3])
        : "r"(a[0]), "r"(a[1]), "r"(a[2]), "r"(a[3]), "r"(b0), "r"(b1));
}
__device__ __forceinline__ unsigned long long pk2(float x, float y) {
    unsigned long long r;
    asm("mov.b64 %0, {%1, %2};" : "=l"(r) : "f"(x), "f"(y));
    return r;
}
__device__ __forceinline__ void upk2(unsigned long long v, float& x, float& y) {
    asm("mov.b64 {%0, %1}, %2;" : "=f"(x), "=f"(y) : "l"(v));
}
__device__ __forceinline__ unsigned long long fma2(unsigned long long a,
                                                   unsigned long long b,
                                                   unsigned long long c) {
    unsigned long long d;
    asm("fma.rn.f32x2 %0, %1, %2, %3;" : "=l"(d) : "l"(a), "l"(b), "l"(c));
    return d;
}

// =====================================================================
// prep_w: transpose W1/W2 to [N,K] K-major fp16
// =====================================================================
__global__ void prep_w(const float* __restrict__ W1, const float* __restrict__ W2,
                       __half* __restrict__ w1, __half* __restrict__ w2) {
    const int n = blockIdx.x, k = threadIdx.x;
    w1[n * 256 + k] = __float2half_rn(W1[k * 256 + n]);
    w2[n * 256 + k] = __float2half_rn(W2[k * 256 + n]);
}

// =====================================================================
// k_prep: adj = mean(graph, bands); y1 = adj @ x -> fp16
// =====================================================================
__global__ __launch_bounds__(128)
void k_prep(const float* __restrict__ graph, const float* __restrict__ x,
            float* __restrict__ adj_out, __half* __restrict__ y1) {
    __shared__ float adj_s[900];
    const int tid = threadIdx.x;
    const size_t b = blockIdx.x;

    const float* gp = graph + b * 4500;
    float* ao = adj_out + b * 900;
    for (int e = tid; e < 900; e += 128) {
        float s = 0.2f * (gp[e] + gp[e + 900] + gp[e + 1800] + gp[e + 2700] + gp[e + 3600]);
        adj_s[e] = s;
        ao[e] = s;
    }

    const int j = tid * 2;
    const float* xp = x + b * 7680 + j;
    unsigned long long xr[30];
    #pragma unroll
    for (int k = 0; k < 30; ++k) {
        float2 v = *(const float2*)(xp + (size_t)k * 256);
        xr[k] = pk2(v.x, v.y);
    }
    __syncthreads();

    #pragma unroll 1
    for (int i = 0; i < 30; ++i) {
        unsigned long long acc = 0ULL;
        const float* ar = adj_s + i * 30;
        #pragma unroll
        for (int k = 0; k < 30; ++k) {
            float a = ar[k];
            acc = fma2(pk2(a, a), xr[k], acc);
        }
        float y0, yy;
        upk2(acc, y0, yy);
        *(__half2*)(y1 + (b * 30 + i) * 256 + j) = __floats2half2_rn(y0, yy);
    }
}

// =====================================================================
// GEMM: C[64,256] = A[64,256] @ W[256,256]^T(K-major), fp16 single-pass.
// A resident (32KB); W double-buffered KC=16 (8KB stages), depth-1 prefetch.
// 256 threads, 8 warps (2 warp_m x 4 warp_n), warp tile 32x64, 2 CTAs/SM.
// MODE 1: Out = relu(C+bias) -> fp16
// MODE 2: Out = C -> fp16
// smem: A [0,32768) 4 chunks [64x128B] SW128; W [32768,49152); bias [49152)
// =====================================================================
#define GSM_A    0u
#define GSM_W    32768u
#define GSM_BIAS 49152u
#define GSM_TOTAL 50176

template <int MODE>
__global__ __launch_bounds__(256, 2)
void gemm_hmma(const __half* __restrict__ A, const __half* __restrict__ W,
               const float* __restrict__ bias, __half* __restrict__ Out) {
    extern __shared__ char smem[];
    const uint32_t sb = smem_to_u32(smem);
    const int tid = threadIdx.x, lane = tid & 31, wid = tid >> 5;
    const int warp_m = wid & 1, warp_n = wid >> 1;
    const size_t arow0 = (size_t)blockIdx.x * 64;

    // ---- A resident load (32KB) ----
    {
        const __half* gA = A + arow0 * 256;
        #pragma unroll
        for (int u = tid; u < 2048; u += 256) {
            int row = u >> 5, s = u & 31;
            int c = s >> 3, ss = s & 7;
            uint32_t off = (uint32_t)c * 8192u + (uint32_t)(row * 128)
                         + (((uint32_t)ss * 16u) ^ ((uint32_t)(row & 7) << 4));
            cpasync16(sb + GSM_A + off, gA + (size_t)row * 256 + s * 8);
        }
        asm volatile("cp.async.commit_group;" ::: "memory");
    }
    if (MODE == 1) ((float*)(smem + GSM_BIAS))[tid] = bias[tid];

    // ---- W stage loader: chunk kc covers k [kc*16, kc*16+16) ----
    auto wload = [&](int kc) {
        uint32_t st = sb + GSM_W + (uint32_t)(kc & 1) * 8192u;
        #pragma unroll
        for (int u = tid; u < 512; u += 256) {
            int n = u >> 1, half = u & 1;
            int row = n & 63, sub = n >> 6;
            uint32_t off = (uint32_t)(row * 128)
                         + (((uint32_t)(sub * 32 + half * 16)) ^ ((uint32_t)(row & 7) << 4));
            cpasync16(st + off, W + (size_t)n * 256 + (size_t)kc * 16 + half * 8);
        }
        asm volatile("cp.async.commit_group;" ::: "memory");
    };
    wload(0);

    // ---- ldmatrix addressing ----
    const int matv = lane >> 3;
    const int rA0 = warp_m * 32 + (matv & 1) * 8 + (lane & 7);
    const int kAoff = (matv >> 1) * 16;
    const int nB0 = warp_n * 64 + matv * 8 + (lane & 7);
    const uint32_t xorv = (uint32_t)((lane & 7) << 4);

    float acc[2][8][4];
    #pragma unroll
    for (int m = 0; m < 2; ++m)
        #pragma unroll
        for (int j = 0; j < 8; ++j)
            #pragma unroll
            for (int q = 0; q < 4; ++q) acc[m][j][q] = 0.f;

    #pragma unroll 1
    for (int kc = 0; kc < 16; ++kc) {
        asm volatile("cp.async.wait_group 0;" ::: "memory");
        __syncthreads();
        if (kc + 1 < 16) wload(kc + 1);   // other stage: no hazard, overlaps math

        const uint32_t wst = sb + GSM_W + (uint32_t)(kc & 1) * 8192u;
        const uint32_t abase = sb + GSM_A + (uint32_t)(kc >> 2) * 8192u;
        const uint32_t aco = ((uint32_t)((kc & 3) * 32 + kAoff)) ^ xorv;

        uint32_t a_f[2][4];
        #pragma unroll
        for (int mt = 0; mt < 2; ++mt)
            ldsm4(a_f[mt], abase + (uint32_t)((rA0 + mt * 16) * 128) + aco);

        #pragma unroll
        for (int jb = 0; jb < 2; ++jb) {
            const int n = nB0 + jb * 32;
            const uint32_t ro = (uint32_t)((n & 63) * 128);
            const uint32_t base = (uint32_t)((n >> 6) * 32);
            uint32_t b0[4], b1[4];
            ldsm4(b0, wst + ro + (base ^ xorv));
            ldsm4(b1, wst + ro + ((base + 16u) ^ xorv));
            #pragma unroll
            for (int mt = 0; mt < 2; ++mt)
                #pragma unroll
                for (int jj = 0; jj < 4; ++jj)
                    mma_f16(acc[mt][jb * 4 + jj], a_f[mt], b0[jj], b1[jj]);
        }
    }

    // ---- epilogue ----
    const int g = lane >> 2, cq = (lane & 3) * 2;
    #pragma unroll
    for (int mt = 0; mt < 2; ++mt) {
        const size_t r0 = arow0 + warp_m * 32 + mt * 16 + g;
        #pragma unroll
        for (int j = 0; j < 8; ++j) {
            const int col = warp_n * 64 + j * 8 + cq;
            if (MODE == 1) {
                const float* bs = (const float*)(smem + GSM_BIAS);
                float bb0 = bs[col], bb1 = bs[col + 1];
                *(__half2*)(Out + r0 * 256 + col) = __floats2half2_rn(
                    fmaxf(acc[mt][j][0] + bb0, 0.f), fmaxf(acc[mt][j][1] + bb1, 0.f));
                *(__half2*)(Out + (r0 + 8) * 256 + col) = __floats2half2_rn(
                    fmaxf(acc[mt][j][2] + bb0, 0.f), fmaxf(acc[mt][j][3] + bb1, 0.f));
            } else {
                *(__half2*)(Out + r0 * 256 + col) =
                    __floats2half2_rn(acc[mt][j][0], acc[mt][j][1]);
                *(__half2*)(Out + (r0 + 8) * 256 + col) =
                    __floats2half2_rn(acc[mt][j][2], acc[mt][j][3]);
            }
        }
    }
}

// =====================================================================
// k_final: g2 = adj @ u2; p = relu(g2+b2).wlin; xl = relu(p+blin);
//          out = xl @ W_head^T + b_head.  u2 in fp16.
// =====================================================================
__global__ __launch_bounds__(512)
void k_final(const float* __restrict__ adj, const __half* __restrict__ u2,
             const float* __restrict__ b2g, const float* __restrict__ wling,
             const float* __restrict__ bling, const float* __restrict__ Wheadg,
             const float* __restrict__ bheadg, float* __restrict__ out) {
    __shared__ float adj_s[4 * 960];
    __shared__ float red[4][30][4];
    const int tid = threadIdx.x;
    const int b = tid >> 7, t2 = tid & 127, w = t2 >> 5;
    const size_t b0 = (size_t)blockIdx.x * 4;

    for (int e = tid; e < 3600; e += 512) {
        int bb = e / 900, i = e - bb * 900;
        adj_s[bb * 960 + (i / 30) * 32 + (i % 30)] = adj[(b0 + bb) * 900 + i];
    }

    const int j = t2 * 2;
    const __half* up = u2 + (b0 + b) * 7680 + j;
    unsigned long long uk[30];
    #pragma unroll
    for (int k = 0; k < 30; ++k) {
        float2 v = __half22float2(*(const __half2*)(up + (size_t)k * 256));
        uk[k] = pk2(v.x, v.y);
    }
    const float b2v0 = __ldg(b2g + j), b2v1 = __ldg(b2g + j + 1);
    const float wl0 = __ldg(wling + j), wl1 = __ldg(wling + j + 1);
    __syncthreads();

    const float* ar = adj_s + b * 960;
    #pragma unroll 1
    for (int i = 0; i < 30; ++i) {
        unsigned long long acc = 0ULL;
        #pragma unroll
        for (int k = 0; k < 30; ++k) {
            float a = ar[i * 32 + k];
            acc = fma2(pk2(a, a), uk[k], acc);
        }
        float s0, s1;
        upk2(acc, s0, s1);
        float p = fmaxf(s0 + b2v0, 0.f) * wl0 + fmaxf(s1 + b2v1, 0.f) * wl1;
        #pragma unroll
        for (int o = 16; o > 0; o >>= 1) p += __shfl_xor_sync(0xffffffffu, p, o);
        if ((t2 & 31) == 0) red[b][i][w] = p;
    }
    __syncthreads();

    if (tid < 36) {
        const int bb = tid / 9, c = tid - bb * 9;
        const float bl = __ldg(bling);
        float s = __ldg(bheadg + c);
        #pragma unroll
        for (int i = 0; i < 30; ++i) {
            float xl = fmaxf(red[bb][i][0] + red[bb][i][1] + red[bb][i][2] + red[bb][i][3] + bl, 0.f);
            s = fmaf(xl, __ldg(Wheadg + c * 30 + i), s);
        }
        out[(b0 + bb) * 9 + c] = s;
    }
}

// =====================================================================
extern "C" void kernel_launch(void* const* d_in, const int* in_sizes, int n_in,
                              void* d_out, int out_size) {
    const float* real  = (const float*)d_in[0];
    const float* graph = (const float*)d_in[2];
    const float* W1    = (const float*)d_in[3];
    const float* b1    = (const float*)d_in[4];
    const float* W2    = (const float*)d_in[5];
    const float* b2    = (const float*)d_in[6];
    const float* wlin  = (const float*)d_in[7];
    const float* blin  = (const float*)d_in[8];
    const float* Whead = (const float*)d_in[9];
    const float* bhead = (const float*)d_in[10];
    float* out = (float*)d_out;

    float *adj_p;
    __half *y1_p, *h1_p, *u2_p, *w1_p, *w2_p;
    cudaGetSymbolAddress((void**)&adj_p, g_adj);
    cudaGetSymbolAddress((void**)&y1_p,  g_y1);
    cudaGetSymbolAddress((void**)&h1_p,  g_h1);
    cudaGetSymbolAddress((void**)&u2_p,  g_u2);
    cudaGetSymbolAddress((void**)&w1_p,  g_w1);
    cudaGetSymbolAddress((void**)&w2_p,  g_w2);

    cudaFuncSetAttribute(gemm_hmma<1>, cudaFuncAttributeMaxDynamicSharedMemorySize, GSM_TOTAL);
    cudaFuncSetAttribute(gemm_hmma<2>, cudaFuncAttributeMaxDynamicSharedMemorySize, GSM_TOTAL);

    // 1. weight transpose to fp16 [N,K]
    prep_w<<<256, 256>>>(W1, W2, w1_p, w2_p);
    // 2. adj = mean(graph); y1 = adj @ real (fp16)
    k_prep<<<BATCH, 128>>>(graph, real, adj_p, y1_p);
    // 3. h1 = relu(y1 @ W1 + b1) (fp16)
    gemm_hmma<1><<<MROWS / 64, 256, GSM_TOTAL>>>(y1_p, w1_p, b1, h1_p);
    // 4. u2 = h1 @ W2 (fp16)
    gemm_hmma<2><<<MROWS / 64, 256, GSM_TOTAL>>>(h1_p, w2_p, nullptr, u2_p);
    // 5. fused: g2 = adj@u2; relu(+b2).wlin; relu(+blin); head -> out
    k_final<<<BATCH / 4, 512>>>(adj_p, u2_p, b2, wlin, blin, Whead, bhead, out);
}

// round 10
// speedup vs baseline: 1.9815x; 1.1392x over previous
#include <cuda_runtime.h>
#include <cuda_fp16.h>
#include <cstdint>

#define BATCH 8192
#define NNODE 30
#define FEAT  256
#define MROWS (BATCH * NNODE)   // 245760
#define NTILES (MROWS / 64)     // 3840
#define PGRID 148

// ---------------- scratch (device globals) ----------------
__device__ float  g_adj[(size_t)BATCH * NNODE * NNODE];  // 29.5 MB
__device__ __half g_y1[(size_t)MROWS * FEAT];
__device__ __half g_h1[(size_t)MROWS * FEAT];
__device__ __half g_u2[(size_t)MROWS * FEAT];
__device__ __half g_w1[FEAT * FEAT], g_w2[FEAT * FEAT];

// ==================== helpers ====================
__device__ __forceinline__ uint32_t smem_to_u32(const void* p) {
    uint32_t a;
    asm("{ .reg .u64 t; cvta.to.shared.u64 t, %1; cvt.u32.u64 %0, t; }" : "=r"(a) : "l"(p));
    return a;
}
__device__ __forceinline__ void cpasync16(uint32_t saddr, const void* g) {
    asm volatile("cp.async.cg.shared.global [%0], [%1], 16;" :: "r"(saddr), "l"(g));
}
__device__ __forceinline__ void ldsm4(uint32_t* r, uint32_t addr) {
    asm volatile("ldmatrix.sync.aligned.m8n8.x4.shared.b16 {%0,%1,%2,%3}, [%4];"
        : "=r"(r[0]), "=r"(r[1]), "=r"(r[2]), "=r"(r[3]) : "r"(addr));
}
__device__ __forceinline__ void mma_f16(float* d, const uint32_t* a, uint32_t b0, uint32_t b1) {
    asm volatile(
        "mma.sync.aligned.m16n8k16.row.col.f32.f16.f16.f32 "
        "{%0,%1,%2,%3}, {%4,%5,%6,%7}, {%8,%9}, {%0,%1,%2,%3};"
        : "+f"(d[0]), "+f"(d[1]), "+f"(d[2]), "+f"(d[3])
        : "r"(a[0]), "r"(a[1]), "r"(a[2]), "r"(a[3]), "r"(b0), "r"(b1));
}
__device__ __forceinline__ unsigned long long pk2(float x, float y) {
    unsigned long long r;
    asm("mov.b64 %0, {%1, %2};" : "=l"(r) : "f"(x), "f"(y));
    return r;
}
__device__ __forceinline__ void upk2(unsigned long long v, float& x, float& y) {
    asm("mov.b64 {%0, %1}, %2;" : "=f"(x), "=f"(y) : "l"(v));
}
__device__ __forceinline__ unsigned long long fma2(unsigned long long a,
                                                   unsigned long long b,
                                                   unsigned long long c) {
    unsigned long long d;
    asm("fma.rn.f32x2 %0, %1, %2, %3;" : "=l"(d) : "l"(a), "l"(b), "l"(c));
    return d;
}

// =====================================================================
// prep_w: transpose W1/W2 to [N,K] K-major fp16
// =====================================================================
__global__ void prep_w(const float* __restrict__ W1, const float* __restrict__ W2,
                       __half* __restrict__ w1, __half* __restrict__ w2) {
    const int n = blockIdx.x, k = threadIdx.x;
    w1[n * 256 + k] = __float2half_rn(W1[k * 256 + n]);
    w2[n * 256 + k] = __float2half_rn(W2[k * 256 + n]);
}

// =====================================================================
// k_prep: adj = mean(graph, bands); y1 = adj @ x -> fp16
// =====================================================================
__global__ __launch_bounds__(128)
void k_prep(const float* __restrict__ graph, const float* __restrict__ x,
            float* __restrict__ adj_out, __half* __restrict__ y1) {
    __shared__ float adj_s[900];
    const int tid = threadIdx.x;
    const size_t b = blockIdx.x;

    const float* gp = graph + b * 4500;
    float* ao = adj_out + b * 900;
    for (int e = tid; e < 900; e += 128) {
        float s = 0.2f * (gp[e] + gp[e + 900] + gp[e + 1800] + gp[e + 2700] + gp[e + 3600]);
        adj_s[e] = s;
        ao[e] = s;
    }

    const int j = tid * 2;
    const float* xp = x + b * 7680 + j;
    unsigned long long xr[30];
    #pragma unroll
    for (int k = 0; k < 30; ++k) {
        float2 v = *(const float2*)(xp + (size_t)k * 256);
        xr[k] = pk2(v.x, v.y);
    }
    __syncthreads();

    #pragma unroll 1
    for (int i = 0; i < 30; ++i) {
        unsigned long long acc = 0ULL;
        const float* ar = adj_s + i * 30;
        #pragma unroll
        for (int k = 0; k < 30; ++k) {
            float a = ar[k];
            acc = fma2(pk2(a, a), xr[k], acc);
        }
        float y0, yy;
        upk2(acc, y0, yy);
        *(__half2*)(y1 + (b * 30 + i) * 256 + j) = __floats2half2_rn(y0, yy);
    }
}

// =====================================================================
// Persistent GEMM: C[64-tile,256] = A @ W^T(K-major), fp16, W RESIDENT.
// grid=148 (1 CTA/SM), 512 threads / 16 warps (2 warp_m x 8 warp_n),
// warp tile 32x32. W loaded once (128KB smem); A double-buffered 32KB
// tiles via grid-stride loop, ONE barrier per tile (128 HMMA/warp between).
// MODE 1: Out = relu(C+bias) -> fp16 ;  MODE 2: Out = C -> fp16
// smem: W [0,131072) 16 chunks of 8KB (per-chunk packed rows);
//       A [131072, +2x32768); bias [196608, 197632)
// =====================================================================
#define PSM_W    0u
#define PSM_A    131072u
#define PSM_BIAS 196608u
#define PSM_TOTAL 197632

template <int MODE>
__global__ __launch_bounds__(512, 1)
void gemm_persist(const __half* __restrict__ A, const __half* __restrict__ W,
                  const float* __restrict__ bias, __half* __restrict__ Out) {
    extern __shared__ char smem[];
    const uint32_t sb = smem_to_u32(smem);
    const int tid = threadIdx.x, lane = tid & 31, wid = tid >> 5;
    const int warp_m = wid & 1, warp_n = wid >> 1;   // 2 x 8

    // ---- W resident load: 16 chunks x 8KB. chunk kc = k[kc*16, +16) ----
    // chunk layout: row r (n&63) 128B: n = r, r+64, r+128, r+192, 32B each
    #pragma unroll
    for (int u = tid; u < 8192; u += 512) {
        int kc = u >> 9, v = u & 511;
        int n = v >> 1, half = v & 1;
        int row = n & 63, sub = n >> 6;
        uint32_t off = (uint32_t)kc * 8192u + (uint32_t)(row * 128)
                     + (((uint32_t)(sub * 32 + half * 16)) ^ ((uint32_t)(row & 7) << 4));
        cpasync16(sb + PSM_W + off, W + (size_t)n * 256 + (size_t)kc * 16 + half * 8);
    }
    asm volatile("cp.async.commit_group;" ::: "memory");
    if (MODE == 1 && tid < 256) ((float*)(smem + PSM_BIAS))[tid] = bias[tid];

    // ---- A tile loader: 32KB = 4 chunks [64 x 128B] SW128 ----
    auto aload = [&](int tile, int stage) {
        const __half* gA = A + (size_t)tile * 64 * 256;
        uint32_t st = sb + PSM_A + (uint32_t)stage * 32768u;
        #pragma unroll
        for (int u = tid; u < 2048; u += 512) {
            int row = u >> 5, s = u & 31;
            int c = s >> 3, ss = s & 7;
            uint32_t off = (uint32_t)c * 8192u + (uint32_t)(row * 128)
                         + (((uint32_t)ss * 16u) ^ ((uint32_t)(row & 7) << 4));
            cpasync16(st + off, gA + (size_t)row * 256 + s * 8);
        }
        asm volatile("cp.async.commit_group;" ::: "memory");
    };

    // ---- ldmatrix addressing ----
    const int matv = lane >> 3;
    const int rA0 = warp_m * 32 + (matv & 1) * 8 + (lane & 7);
    const int kAoff = (matv >> 1) * 16;
    const int nB0 = warp_n * 32 + matv * 8 + (lane & 7);
    const uint32_t roB = (uint32_t)((nB0 & 63) * 128);
    const uint32_t baseB = (uint32_t)((nB0 >> 6) * 32);
    const uint32_t xorv = (uint32_t)((lane & 7) << 4);
    const int g = lane >> 2, cq = (lane & 3) * 2;

    int tile = blockIdx.x;
    aload(tile, 0);
    int it = 0;

    #pragma unroll 1
    for (; tile < NTILES; tile += PGRID, ++it) {
        const int stage = it & 1;
        asm volatile("cp.async.wait_group 0;" ::: "memory");
        __syncthreads();
        if (tile + PGRID < NTILES) aload(tile + PGRID, stage ^ 1);

        const uint32_t ab = sb + PSM_A + (uint32_t)stage * 32768u;
        float acc[2][4][4];
        #pragma unroll
        for (int m = 0; m < 2; ++m)
            #pragma unroll
            for (int j = 0; j < 4; ++j)
                #pragma unroll
                for (int q = 0; q < 4; ++q) acc[m][j][q] = 0.f;

        #pragma unroll 4
        for (int kc = 0; kc < 16; ++kc) {
            const uint32_t abase = ab + (uint32_t)(kc >> 2) * 8192u;
            const uint32_t aco = ((uint32_t)((kc & 3) * 32 + kAoff)) ^ xorv;
            uint32_t a_f[2][4];
            #pragma unroll
            for (int mt = 0; mt < 2; ++mt)
                ldsm4(a_f[mt], abase + (uint32_t)((rA0 + mt * 16) * 128) + aco);

            const uint32_t wst = sb + PSM_W + (uint32_t)kc * 8192u;
            uint32_t b0[4], b1[4];
            ldsm4(b0, wst + roB + (baseB ^ xorv));
            ldsm4(b1, wst + roB + ((baseB + 16u) ^ xorv));
            #pragma unroll
            for (int mt = 0; mt < 2; ++mt)
                #pragma unroll
                for (int jj = 0; jj < 4; ++jj)
                    mma_f16(acc[mt][jj], a_f[mt], b0[jj], b1[jj]);
        }

        // ---- epilogue ----
        #pragma unroll
        for (int mt = 0; mt < 2; ++mt) {
            const size_t r0 = (size_t)tile * 64 + warp_m * 32 + mt * 16 + g;
            #pragma unroll
            for (int j = 0; j < 4; ++j) {
                const int col = warp_n * 32 + j * 8 + cq;
                if (MODE == 1) {
                    const float* bs = (const float*)(smem + PSM_BIAS);
                    float bb0 = bs[col], bb1 = bs[col + 1];
                    *(__half2*)(Out + r0 * 256 + col) = __floats2half2_rn(
                        fmaxf(acc[mt][j][0] + bb0, 0.f), fmaxf(acc[mt][j][1] + bb1, 0.f));
                    *(__half2*)(Out + (r0 + 8) * 256 + col) = __floats2half2_rn(
                        fmaxf(acc[mt][j][2] + bb0, 0.f), fmaxf(acc[mt][j][3] + bb1, 0.f));
                } else {
                    *(__half2*)(Out + r0 * 256 + col) =
                        __floats2half2_rn(acc[mt][j][0], acc[mt][j][1]);
                    *(__half2*)(Out + (r0 + 8) * 256 + col) =
                        __floats2half2_rn(acc[mt][j][2], acc[mt][j][3]);
                }
            }
        }
    }
}

// =====================================================================
// k_final: g2 = adj @ u2; p = relu(g2+b2).wlin; xl = relu(p+blin);
//          out = xl @ W_head^T + b_head.  u2 in fp16.
// =====================================================================
__global__ __launch_bounds__(512)
void k_final(const float* __restrict__ adj, const __half* __restrict__ u2,
             const float* __restrict__ b2g, const float* __restrict__ wling,
             const float* __restrict__ bling, const float* __restrict__ Wheadg,
             const float* __restrict__ bheadg, float* __restrict__ out) {
    __shared__ float adj_s[4 * 960];
    __shared__ float red[4][30][4];
    const int tid = threadIdx.x;
    const int b = tid >> 7, t2 = tid & 127, w = t2 >> 5;
    const size_t b0 = (size_t)blockIdx.x * 4;

    for (int e = tid; e < 3600; e += 512) {
        int bb = e / 900, i = e - bb * 900;
        adj_s[bb * 960 + (i / 30) * 32 + (i % 30)] = adj[(b0 + bb) * 900 + i];
    }

    const int j = t2 * 2;
    const __half* up = u2 + (b0 + b) * 7680 + j;
    unsigned long long uk[30];
    #pragma unroll
    for (int k = 0; k < 30; ++k) {
        float2 v = __half22float2(*(const __half2*)(up + (size_t)k * 256));
        uk[k] = pk2(v.x, v.y);
    }
    const float b2v0 = __ldg(b2g + j), b2v1 = __ldg(b2g + j + 1);
    const float wl0 = __ldg(wling + j), wl1 = __ldg(wling + j + 1);
    __syncthreads();

    const float* ar = adj_s + b * 960;
    #pragma unroll 1
    for (int i = 0; i < 30; ++i) {
        unsigned long long acc = 0ULL;
        #pragma unroll
        for (int k = 0; k < 30; ++k) {
            float a = ar[i * 32 + k];
            acc = fma2(pk2(a, a), uk[k], acc);
        }
        float s0, s1;
        upk2(acc, s0, s1);
        float p = fmaxf(s0 + b2v0, 0.f) * wl0 + fmaxf(s1 + b2v1, 0.f) * wl1;
        #pragma unroll
        for (int o = 16; o > 0; o >>= 1) p += __shfl_xor_sync(0xffffffffu, p, o);
        if ((t2 & 31) == 0) red[b][i][w] = p;
    }
    __syncthreads();

    if (tid < 36) {
        const int bb = tid / 9, c = tid - bb * 9;
        const float bl = __ldg(bling);
        float s = __ldg(bheadg + c);
        #pragma unroll
        for (int i = 0; i < 30; ++i) {
            float xl = fmaxf(red[bb][i][0] + red[bb][i][1] + red[bb][i][2] + red[bb][i][3] + bl, 0.f);
            s = fmaf(xl, __ldg(Wheadg + c * 30 + i), s);
        }
        out[(b0 + bb) * 9 + c] = s;
    }
}

// =====================================================================
extern "C" void kernel_launch(void* const* d_in, const int* in_sizes, int n_in,
                              void* d_out, int out_size) {
    const float* real  = (const float*)d_in[0];
    const float* graph = (const float*)d_in[2];
    const float* W1    = (const float*)d_in[3];
    const float* b1    = (const float*)d_in[4];
    const float* W2    = (const float*)d_in[5];
    const float* b2    = (const float*)d_in[6];
    const float* wlin  = (const float*)d_in[7];
    const float* blin  = (const float*)d_in[8];
    const float* Whead = (const float*)d_in[9];
    const float* bhead = (const float*)d_in[10];
    float* out = (float*)d_out;

    float *adj_p;
    __half *y1_p, *h1_p, *u2_p, *w1_p, *w2_p;
    cudaGetSymbolAddress((void**)&adj_p, g_adj);
    cudaGetSymbolAddress((void**)&y1_p,  g_y1);
    cudaGetSymbolAddress((void**)&h1_p,  g_h1);
    cudaGetSymbolAddress((void**)&u2_p,  g_u2);
    cudaGetSymbolAddress((void**)&w1_p,  g_w1);
    cudaGetSymbolAddress((void**)&w2_p,  g_w2);

    cudaFuncSetAttribute(gemm_persist<1>, cudaFuncAttributeMaxDynamicSharedMemorySize, PSM_TOTAL);
    cudaFuncSetAttribute(gemm_persist<2>, cudaFuncAttributeMaxDynamicSharedMemorySize, PSM_TOTAL);

    // 1. weight transpose to fp16 [N,K]
    prep_w<<<256, 256>>>(W1, W2, w1_p, w2_p);
    // 2. adj = mean(graph); y1 = adj @ real (fp16)
    k_prep<<<BATCH, 128>>>(graph, real, adj_p, y1_p);
    // 3. h1 = relu(y1 @ W1 + b1)  (persistent, W1 resident)
    gemm_persist<1><<<PGRID, 512, PSM_TOTAL>>>(y1_p, w1_p, b1, h1_p);
    // 4. u2 = h1 @ W2             (persistent, W2 resident)
    gemm_persist<2><<<PGRID, 512, PSM_TOTAL>>>(h1_p, w2_p, nullptr, u2_p);
    // 5. fused: g2 = adj@u2; relu(+b2).wlin; relu(+blin); head -> out
    k_final<<<BATCH / 4, 512>>>(adj_p, u2_p, b2, wlin, blin, Whead, bhead, out);
}